// round 10
// baseline (speedup 1.0000x reference)
#include <cuda_runtime.h>
#include <cuda_fp16.h>
#include <cstdint>

// GCN link prediction, round 10: ONE persistent kernel.
//  - 592 blocks (4/SM guaranteed co-resident), device-wide barriers between
//    phases, atomic work queues for load balancing
//  - phases: init | gemm1+fill (block-split, overlapped) | norm1 | gather1+GEMM2
//    | gather2 | decode
//  - fp16 y rows, padded adjacency CAP=128, FFMA2 gemm

#define NMAX  100000
#define EMAX  3200000
#define F_IN  128
#define H1    32
#define H2    16
#define CAP   128
#define CAPSH 7
#define NBLK  592
#define NTHR  256
#define NTHREADS (NBLK * NTHR)
#define GEMM_BLOCKS 128

__device__ __align__(16) int    g_cnt [NMAX];
__device__ __align__(16) int    g_epad[NMAX * CAP];
__device__ __align__(16) __half g_y1h[NMAX * H1];
__device__ __align__(16) __half g_y2h[NMAX * H2];
__device__ __align__(16) float  g_z  [NMAX * H2];
__device__ unsigned g_wq[8];
__device__ unsigned g_barCnt;
__device__ volatile unsigned g_barGen;

__device__ __forceinline__ void fma2(unsigned long long& acc,
                                     unsigned long long a, unsigned long long b) {
    asm("fma.rn.f32x2 %0, %1, %2, %0;" : "+l"(acc) : "l"(a), "l"(b));
}
__device__ __forceinline__ unsigned long long pack2(float lo, float hi) {
    unsigned long long r;
    asm("mov.b64 %0, {%1, %2};" : "=l"(r) : "f"(lo), "f"(hi));
    return r;
}
__device__ __forceinline__ float2 unpack2(unsigned long long v) {
    float2 r;
    asm("mov.b64 {%0, %1}, %2;" : "=f"(r.x), "=f"(r.y) : "l"(v));
    return r;
}
__device__ __forceinline__ uint32_t h2bits(float a, float b) {
    __half2 h = __floats2half2_rn(a, b);
    return *(uint32_t*)&h;
}
__device__ __forceinline__ float2 bits2f(uint32_t u) {
    return __half22float2(*(__half2*)&u);
}

__device__ __forceinline__ void gridBarrier() {
    __syncthreads();
    if (threadIdx.x == 0) {
        unsigned gen = g_barGen;
        __threadfence();
        if (atomicAdd(&g_barCnt, 1u) == (unsigned)(NBLK - 1)) {
            atomicExch(&g_barCnt, 0u);
            __threadfence();
            g_barGen = gen + 1u;
        } else {
            while (g_barGen == gen) __nanosleep(64);
        }
        __threadfence();
    }
    __syncthreads();
}

__global__ void __launch_bounds__(NTHR, 4)
k_all(const float* __restrict__ x,  const float* __restrict__ W1,
      const float* __restrict__ b1, const float* __restrict__ W2,
      const float* __restrict__ b2,
      const int* __restrict__ src,  const int* __restrict__ dst,
      const int* __restrict__ ea,   const int* __restrict__ eb,
      float* __restrict__ out, int n, int E, int L) {

    __shared__ __align__(16) unsigned char smraw[16384];
    __shared__ int unitSh;

    int tid = threadIdx.x;
    int bid = blockIdx.x;
    int gt  = bid * NTHR + tid;

    // ---------------- phase 0: init ----------------
    for (int t = gt; t < n; t += NTHREADS) g_cnt[t] = 0;
    if (bid == 0 && tid < 8) g_wq[tid] = 0u;
    gridBarrier();

    // ---------------- phase 1: gemm1 + fill (overlapped via block split) ----
    {
        int nFillItems = E / 8;                       // 400000
        int nFillUnits = (nFillItems + NTHR - 1) / NTHR;
        int nGemmUnits = (n + NTHR - 1) / NTHR;

        if (bid < GEMM_BLOCKS) {
            // load W1 into smem once
            ulonglong2* Ws = (ulonglong2*)smraw;
            const ulonglong2* W1u = (const ulonglong2*)W1;
            #pragma unroll 4
            for (int i = tid; i < F_IN * 8; i += NTHR) Ws[i] = W1u[i];
            // gemm queue
            for (;;) {
                __syncthreads();
                if (tid == 0) unitSh = (int)atomicAdd(&g_wq[0], 1u);
                __syncthreads();
                int unit = unitSh;
                if (unit >= nGemmUnits) break;
                int node = unit * NTHR + tid;
                if (node >= n) continue;
                const float4* xr = (const float4*)(x + (size_t)node * F_IN);
                unsigned long long acc[16];
                #pragma unroll
                for (int i = 0; i < 16; i++) acc[i] = 0ull;
                #pragma unroll
                for (int chunk = 0; chunk < 4; chunk++) {
                    float4 xv[8];
                    #pragma unroll
                    for (int p = 0; p < 8; p++) xv[p] = xr[chunk * 8 + p];
                    #pragma unroll
                    for (int p = 0; p < 8; p++) {
                        float xk[4] = {xv[p].x, xv[p].y, xv[p].z, xv[p].w};
                        #pragma unroll
                        for (int kk = 0; kk < 4; kk++) {
                            int k = chunk * 32 + p * 4 + kk;
                            unsigned long long xp = pack2(xk[kk], xk[kk]);
                            #pragma unroll
                            for (int q = 0; q < 8; q++) {
                                ulonglong2 w = Ws[k * 8 + q];
                                fma2(acc[q * 2],     xp, w.x);
                                fma2(acc[q * 2 + 1], xp, w.y);
                            }
                        }
                    }
                }
                uint4* yv = (uint4*)(g_y1h + (size_t)node * H1);
                #pragma unroll
                for (int q4 = 0; q4 < 4; q4++) {
                    float2 a = unpack2(acc[q4 * 4 + 0]);
                    float2 b = unpack2(acc[q4 * 4 + 1]);
                    float2 c = unpack2(acc[q4 * 4 + 2]);
                    float2 d = unpack2(acc[q4 * 4 + 3]);
                    uint4 o;
                    o.x = h2bits(a.x, a.y);
                    o.y = h2bits(b.x, b.y);
                    o.z = h2bits(c.x, c.y);
                    o.w = h2bits(d.x, d.y);
                    yv[q4] = o;
                }
            }
        }
        // everyone (fill blocks immediately, gemm blocks after gemm) drains fill
        for (;;) {
            __syncthreads();
            if (tid == 0) unitSh = (int)atomicAdd(&g_wq[1], 1u);
            __syncthreads();
            int unit = unitSh;
            if (unit >= nFillUnits) break;
            int t = unit * NTHR + tid;
            if (t >= nFillItems) continue;
            int4 d0 = ((const int4*)dst)[t * 2];
            int4 d1 = ((const int4*)dst)[t * 2 + 1];
            int4 s0 = ((const int4*)src)[t * 2];
            int4 s1 = ((const int4*)src)[t * 2 + 1];
            int dd[8] = {d0.x, d0.y, d0.z, d0.w, d1.x, d1.y, d1.z, d1.w};
            int ss[8] = {s0.x, s0.y, s0.z, s0.w, s1.x, s1.y, s1.z, s1.w};
            int pos[8];
            #pragma unroll
            for (int u = 0; u < 8; u++) pos[u] = atomicAdd(&g_cnt[dd[u]], 1);
            #pragma unroll
            for (int u = 0; u < 8; u++) {
                int p = pos[u] < CAP ? pos[u] : (CAP - 1);
                g_epad[(dd[u] << CAPSH) + p] = ss[u];
            }
        }
    }
    gridBarrier();

    // ---------------- phase 2: norm1 (y1h *= rsqrt(deg+1)) ----------------
    for (int t = gt; t < n * 4; t += NTHREADS) {
        int node = t >> 2;
        int c = t & 3;
        float is = rsqrtf((float)g_cnt[node] + 1.0f);
        uint4* yv = (uint4*)(g_y1h + (size_t)node * H1);
        uint4 v = yv[c];
        float2 f0 = bits2f(v.x), f1 = bits2f(v.y), f2 = bits2f(v.z), f3 = bits2f(v.w);
        uint4 o;
        o.x = h2bits(f0.x * is, f0.y * is);
        o.y = h2bits(f1.x * is, f1.y * is);
        o.z = h2bits(f2.x * is, f2.y * is);
        o.w = h2bits(f3.x * is, f3.y * is);
        yv[c] = o;
    }
    gridBarrier();

    // ---------------- phase 3: gather1 + relu/bias + GEMM2 -> y2h ----------
    {
        float* Ws2 = (float*)smraw;            // [H1*H2]
        float* bsS = Ws2 + H1 * H2;            // [H1]
        float* hs  = bsS + H1;                 // [64][H1+2]
        if (tid < H1 * H2 / 2) ((float2*)Ws2)[tid] = ((const float2*)W2)[tid];
        if (tid < H1) bsS[tid] = b1[tid];

        int nUnits = (n + 63) / 64;
        const uint4* y1v = (const uint4*)g_y1h;
        const int4* epad4 = (const int4*)g_epad;
        int g = tid >> 2;
        int c = tid & 3;

        for (;;) {
            __syncthreads();
            if (tid == 0) unitSh = (int)atomicAdd(&g_wq[2], 1u);
            __syncthreads();
            int unit = unitSh;
            if (unit >= nUnits) break;
            int node = unit * 64 + g;

            float acc[8];
            #pragma unroll
            for (int i = 0; i < 8; i++) acc[i] = 0.f;
            float is = 0.f;
            int deg = 0;
            int base4 = node << (CAPSH - 2);

            if (node < n) {
                uint4 self = y1v[node * 4 + c];
                float2 f0 = bits2f(self.x), f1 = bits2f(self.y),
                       f2 = bits2f(self.z), f3 = bits2f(self.w);
                acc[0] = f0.x; acc[1] = f0.y; acc[2] = f1.x; acc[3] = f1.y;
                acc[4] = f2.x; acc[5] = f2.y; acc[6] = f3.x; acc[7] = f3.y;
                deg = g_cnt[node];
                is = rsqrtf((float)deg + 1.0f);
            }

            int j = 0;
            for (; j + 8 <= deg; j += 8) {
                int4 i0 = __ldg(&epad4[base4 + (j >> 2)]);
                int4 i1 = __ldg(&epad4[base4 + (j >> 2) + 1]);
                int s[8] = {i0.x, i0.y, i0.z, i0.w, i1.x, i1.y, i1.z, i1.w};
                uint4 v[8];
                #pragma unroll
                for (int u = 0; u < 8; u++) v[u] = y1v[s[u] * 4 + c];
                #pragma unroll
                for (int u = 0; u < 8; u++) {
                    float2 f0 = bits2f(v[u].x), f1 = bits2f(v[u].y),
                           f2 = bits2f(v[u].z), f3 = bits2f(v[u].w);
                    acc[0] += f0.x; acc[1] += f0.y; acc[2] += f1.x; acc[3] += f1.y;
                    acc[4] += f2.x; acc[5] += f2.y; acc[6] += f3.x; acc[7] += f3.y;
                }
            }
            if (j < deg) {
                int4 i0 = __ldg(&epad4[base4 + (j >> 2)]);
                int4 i1 = __ldg(&epad4[base4 + (j >> 2) + 1]);
                int s[8] = {i0.x, i0.y, i0.z, i0.w, i1.x, i1.y, i1.z, i1.w};
                int rem = deg - j;
                #pragma unroll
                for (int u = 0; u < 8; u++) {
                    if (u < rem) {
                        uint4 v0 = y1v[s[u] * 4 + c];
                        float2 f0 = bits2f(v0.x), f1 = bits2f(v0.y),
                               f2 = bits2f(v0.z), f3 = bits2f(v0.w);
                        acc[0] += f0.x; acc[1] += f0.y; acc[2] += f1.x; acc[3] += f1.y;
                        acc[4] += f2.x; acc[5] += f2.y; acc[6] += f3.x; acc[7] += f3.y;
                    }
                }
            }

            #pragma unroll
            for (int u = 0; u < 8; u++)
                hs[g * (H1 + 2) + c * 8 + u] = fmaxf(fmaf(is, acc[u], bsS[c * 8 + u]), 0.f);
            __syncthreads();

            if (node < n) {
                float a0 = 0.f, a1 = 0.f, a2 = 0.f, a3 = 0.f;
                #pragma unroll
                for (int k = 0; k < H1; k++) {
                    float h = hs[g * (H1 + 2) + k];
                    a0 = fmaf(h, Ws2[k * H2 + c * 4 + 0], a0);
                    a1 = fmaf(h, Ws2[k * H2 + c * 4 + 1], a1);
                    a2 = fmaf(h, Ws2[k * H2 + c * 4 + 2], a2);
                    a3 = fmaf(h, Ws2[k * H2 + c * 4 + 3], a3);
                }
                uint2 o;
                o.x = h2bits(a0 * is, a1 * is);
                o.y = h2bits(a2 * is, a3 * is);
                ((uint2*)(g_y2h + (size_t)node * H2))[c] = o;
            }
        }
    }
    gridBarrier();

    // ---------------- phase 4: gather2 + bias -> z (64 nodes/unit, 4 lanes) --
    {
        float* bs2 = (float*)smraw;            // [H2]
        if (tid < H2) bs2[tid] = b2[tid];

        int nUnits = (n + 63) / 64;
        const uint2* y2v = (const uint2*)g_y2h;
        const int4* epad4 = (const int4*)g_epad;
        int g = tid >> 2;
        int c = tid & 3;

        for (;;) {
            __syncthreads();
            if (tid == 0) unitSh = (int)atomicAdd(&g_wq[3], 1u);
            __syncthreads();
            int unit = unitSh;
            if (unit >= nUnits) break;
            int node = unit * 64 + g;
            if (node >= n) continue;

            int base4 = node << (CAPSH - 2);
            uint2 self = y2v[node * 4 + c];
            float acc[4];
            {
                float2 f0 = bits2f(self.x), f1 = bits2f(self.y);
                acc[0] = f0.x; acc[1] = f0.y; acc[2] = f1.x; acc[3] = f1.y;
            }
            int deg = g_cnt[node];
            float is = rsqrtf((float)deg + 1.0f);

            int j = 0;
            for (; j + 8 <= deg; j += 8) {
                int4 i0 = __ldg(&epad4[base4 + (j >> 2)]);
                int4 i1 = __ldg(&epad4[base4 + (j >> 2) + 1]);
                int s[8] = {i0.x, i0.y, i0.z, i0.w, i1.x, i1.y, i1.z, i1.w};
                uint2 v[8];
                #pragma unroll
                for (int u = 0; u < 8; u++) v[u] = y2v[s[u] * 4 + c];
                #pragma unroll
                for (int u = 0; u < 8; u++) {
                    float2 f0 = bits2f(v[u].x), f1 = bits2f(v[u].y);
                    acc[0] += f0.x; acc[1] += f0.y; acc[2] += f1.x; acc[3] += f1.y;
                }
            }
            if (j < deg) {
                int4 i0 = __ldg(&epad4[base4 + (j >> 2)]);
                int4 i1 = __ldg(&epad4[base4 + (j >> 2) + 1]);
                int s[8] = {i0.x, i0.y, i0.z, i0.w, i1.x, i1.y, i1.z, i1.w};
                int rem = deg - j;
                #pragma unroll
                for (int u = 0; u < 8; u++) {
                    if (u < rem) {
                        uint2 v0 = y2v[s[u] * 4 + c];
                        float2 f0 = bits2f(v0.x), f1 = bits2f(v0.y);
                        acc[0] += f0.x; acc[1] += f0.y; acc[2] += f1.x; acc[3] += f1.y;
                    }
                }
            }

            float4 z;
            z.x = fmaf(is, acc[0], bs2[c * 4 + 0]);
            z.y = fmaf(is, acc[1], bs2[c * 4 + 1]);
            z.z = fmaf(is, acc[2], bs2[c * 4 + 2]);
            z.w = fmaf(is, acc[3], bs2[c * 4 + 3]);
            ((float4*)(g_z + (size_t)node * H2))[c] = z;
        }
    }
    gridBarrier();

    // ---------------- phase 5: decode (4 lanes/edge + shfl) -----------------
    for (int t = gt; t < L * 4; t += NTHREADS) {
        int e = t >> 2;
        int c = t & 3;
        int a = __ldg(&ea[e]);
        int b = __ldg(&eb[e]);
        float4 u = ((const float4*)g_z)[a * 4 + c];
        float4 v = ((const float4*)g_z)[b * 4 + c];
        float s = u.x * v.x + u.y * v.y + u.z * v.z + u.w * v.w;
        s += __shfl_xor_sync(0xffffffffu, s, 1);
        s += __shfl_xor_sync(0xffffffffu, s, 2);
        if (c == 0) out[e] = s;
    }
}

// ---------------------------------------------------------------------------
extern "C" void kernel_launch(void* const* d_in, const int* in_sizes, int n_in,
                              void* d_out, int out_size) {
    const float* x   = (const float*)d_in[0];
    const int*   ei  = (const int*)  d_in[1];
    const int*   eli = (const int*)  d_in[2];
    const float* W1  = (const float*)d_in[3];
    const float* b1  = (const float*)d_in[4];
    const float* W2  = (const float*)d_in[5];
    const float* b2  = (const float*)d_in[6];
    float* out = (float*)d_out;

    int n = in_sizes[0] / F_IN;     // 100000
    int E = in_sizes[1] / 2;        // 3200000
    int L = in_sizes[2] / 2;        // 200000

    const int* src = ei;
    const int* dst = ei + E;
    const int* ea  = eli;
    const int* eb  = eli + L;

    k_all<<<NBLK, NTHR>>>(x, W1, b1, W2, b2, src, dst, ea, eb, out, n, E, L);
}

// round 11
// speedup vs baseline: 1.2756x; 1.2756x over previous
#include <cuda_runtime.h>
#include <cuda_fp16.h>
#include <cstdint>

// GCN link prediction, round 11: R9 structure (separate kernels, fill+gemm1
// fused) with gathers reshaped to 128-thread / 32-node blocks (3125 blocks,
// ~3 waves) so wave>=2 work-stealing absorbs degree/spread imbalance.

#define NMAX  100000
#define EMAX  3200000
#define F_IN  128
#define H1    32
#define H2    16
#define CAP   128
#define CAPSH 7

__device__ __align__(16) int    g_cnt [NMAX];
__device__ __align__(16) int    g_epad[NMAX * CAP];
__device__ __align__(16) __half g_y1h[NMAX * H1];
__device__ __align__(16) __half g_y2h[NMAX * H2];
__device__ __align__(16) float  g_z  [NMAX * H2];

__device__ __forceinline__ void fma2(unsigned long long& acc,
                                     unsigned long long a, unsigned long long b) {
    asm("fma.rn.f32x2 %0, %1, %2, %0;" : "+l"(acc) : "l"(a), "l"(b));
}
__device__ __forceinline__ unsigned long long pack2(float lo, float hi) {
    unsigned long long r;
    asm("mov.b64 %0, {%1, %2};" : "=l"(r) : "f"(lo), "f"(hi));
    return r;
}
__device__ __forceinline__ float2 unpack2(unsigned long long v) {
    float2 r;
    asm("mov.b64 {%0, %1}, %2;" : "=f"(r.x), "=f"(r.y) : "l"(v));
    return r;
}
__device__ __forceinline__ uint32_t h2bits(float a, float b) {
    __half2 h = __floats2half2_rn(a, b);
    return *(uint32_t*)&h;
}
__device__ __forceinline__ float2 bits2f(uint32_t u) {
    return __half22float2(*(__half2*)&u);
}

// ---------------------------------------------------------------------------
// fused gemm1 (blocks [0, gemmBlocks)) + fill (remaining blocks)
__global__ void __launch_bounds__(256) k_fuse(const float* __restrict__ x,
                                              const float* __restrict__ W1,
                                              const int* __restrict__ src,
                                              const int* __restrict__ dst,
                                              int n, int E, int gemmBlocks) {
    __shared__ ulonglong2 Ws[F_IN * 8];
    int tid = threadIdx.x;

    if (blockIdx.x < gemmBlocks) {
        const ulonglong2* W1u = (const ulonglong2*)W1;
        #pragma unroll 4
        for (int i = tid; i < F_IN * 8; i += 256) Ws[i] = W1u[i];
        __syncthreads();

        int node = blockIdx.x * 256 + tid;
        if (node >= n) return;

        const float4* xr = (const float4*)(x + (size_t)node * F_IN);

        unsigned long long acc[16];
        #pragma unroll
        for (int i = 0; i < 16; i++) acc[i] = 0ull;

        #pragma unroll
        for (int chunk = 0; chunk < 4; chunk++) {
            float4 xv[8];
            #pragma unroll
            for (int p = 0; p < 8; p++) xv[p] = xr[chunk * 8 + p];
            #pragma unroll
            for (int p = 0; p < 8; p++) {
                float xk[4] = {xv[p].x, xv[p].y, xv[p].z, xv[p].w};
                #pragma unroll
                for (int kk = 0; kk < 4; kk++) {
                    int k = chunk * 32 + p * 4 + kk;
                    unsigned long long xp = pack2(xk[kk], xk[kk]);
                    #pragma unroll
                    for (int q = 0; q < 8; q++) {
                        ulonglong2 w = Ws[k * 8 + q];
                        fma2(acc[q * 2],     xp, w.x);
                        fma2(acc[q * 2 + 1], xp, w.y);
                    }
                }
            }
        }

        uint4* yv = (uint4*)(g_y1h + (size_t)node * H1);
        #pragma unroll
        for (int q4 = 0; q4 < 4; q4++) {
            float2 a = unpack2(acc[q4 * 4 + 0]);
            float2 b = unpack2(acc[q4 * 4 + 1]);
            float2 c = unpack2(acc[q4 * 4 + 2]);
            float2 d = unpack2(acc[q4 * 4 + 3]);
            uint4 o;
            o.x = h2bits(a.x, a.y);
            o.y = h2bits(b.x, b.y);
            o.z = h2bits(c.x, c.y);
            o.w = h2bits(d.x, d.y);
            yv[q4] = o;
        }
    } else {
        int t = (blockIdx.x - gemmBlocks) * 256 + tid;
        if (t * 8 >= E) return;
        int4 d0 = ((const int4*)dst)[t * 2];
        int4 d1 = ((const int4*)dst)[t * 2 + 1];
        int4 s0 = ((const int4*)src)[t * 2];
        int4 s1 = ((const int4*)src)[t * 2 + 1];

        int dd[8] = {d0.x, d0.y, d0.z, d0.w, d1.x, d1.y, d1.z, d1.w};
        int ss[8] = {s0.x, s0.y, s0.z, s0.w, s1.x, s1.y, s1.z, s1.w};

        int pos[8];
        #pragma unroll
        for (int u = 0; u < 8; u++) pos[u] = atomicAdd(&g_cnt[dd[u]], 1);
        #pragma unroll
        for (int u = 0; u < 8; u++) {
            int p = pos[u] < CAP ? pos[u] : (CAP - 1);
            g_epad[(dd[u] << CAPSH) + p] = ss[u];
        }
    }
}

// ---------------------------------------------------------------------------
__global__ void __launch_bounds__(256) k_norm1(int n) {
    int t = blockIdx.x * 256 + threadIdx.x;
    int node = t >> 2;
    if (node >= n) return;
    int c = t & 3;
    float is = rsqrtf((float)g_cnt[node] + 1.0f);
    uint4* yv = (uint4*)(g_y1h + (size_t)node * H1);
    uint4 v = yv[c];
    float2 f0 = bits2f(v.x), f1 = bits2f(v.y), f2 = bits2f(v.z), f3 = bits2f(v.w);
    uint4 o;
    o.x = h2bits(f0.x * is, f0.y * is);
    o.y = h2bits(f1.x * is, f1.y * is);
    o.z = h2bits(f2.x * is, f2.y * is);
    o.w = h2bits(f3.x * is, f3.y * is);
    yv[c] = o;
}

// ---------------------------------------------------------------------------
// gather1 + relu/bias + GEMM2 -> y2h; 128 threads = 32 nodes x 4 lanes
__global__ void __launch_bounds__(128) k_gather1(const float* __restrict__ b1,
                                                 const float* __restrict__ W2, int n) {
    __shared__ float Ws[H1 * H2];
    __shared__ float bs[H1];
    __shared__ float hs[32][H1 + 2];

    int tid = threadIdx.x;
    for (int i = tid; i < H1 * H2 / 2; i += 128) ((float2*)Ws)[i] = ((const float2*)W2)[i];
    if (tid < H1) bs[tid] = b1[tid];
    __syncthreads();

    int g = tid >> 2;
    int c = tid & 3;
    int node = blockIdx.x * 32 + g;

    float acc[8];
    #pragma unroll
    for (int i = 0; i < 8; i++) acc[i] = 0.f;
    float is = 0.f;
    int deg = 0;
    const uint4* y1v = (const uint4*)g_y1h;
    const int4* epad4 = (const int4*)g_epad;
    int base4 = node << (CAPSH - 2);

    if (node < n) {
        uint4 self = y1v[node * 4 + c];
        float2 f0 = bits2f(self.x), f1 = bits2f(self.y), f2 = bits2f(self.z), f3 = bits2f(self.w);
        acc[0] = f0.x; acc[1] = f0.y; acc[2] = f1.x; acc[3] = f1.y;
        acc[4] = f2.x; acc[5] = f2.y; acc[6] = f3.x; acc[7] = f3.y;
        deg = g_cnt[node];
        is = rsqrtf((float)deg + 1.0f);
    }

    int j = 0;
    for (; j + 8 <= deg; j += 8) {
        int4 i0 = __ldg(&epad4[base4 + (j >> 2)]);
        int4 i1 = __ldg(&epad4[base4 + (j >> 2) + 1]);
        int s[8] = {i0.x, i0.y, i0.z, i0.w, i1.x, i1.y, i1.z, i1.w};
        uint4 v[8];
        #pragma unroll
        for (int u = 0; u < 8; u++) v[u] = y1v[s[u] * 4 + c];
        #pragma unroll
        for (int u = 0; u < 8; u++) {
            float2 f0 = bits2f(v[u].x), f1 = bits2f(v[u].y),
                   f2 = bits2f(v[u].z), f3 = bits2f(v[u].w);
            acc[0] += f0.x; acc[1] += f0.y; acc[2] += f1.x; acc[3] += f1.y;
            acc[4] += f2.x; acc[5] += f2.y; acc[6] += f3.x; acc[7] += f3.y;
        }
    }
    if (j < deg) {
        int4 i0 = __ldg(&epad4[base4 + (j >> 2)]);
        int4 i1 = __ldg(&epad4[base4 + (j >> 2) + 1]);
        int s[8] = {i0.x, i0.y, i0.z, i0.w, i1.x, i1.y, i1.z, i1.w};
        int rem = deg - j;
        #pragma unroll
        for (int u = 0; u < 8; u++) {
            if (u < rem) {
                uint4 v0 = y1v[s[u] * 4 + c];
                float2 f0 = bits2f(v0.x), f1 = bits2f(v0.y),
                       f2 = bits2f(v0.z), f3 = bits2f(v0.w);
                acc[0] += f0.x; acc[1] += f0.y; acc[2] += f1.x; acc[3] += f1.y;
                acc[4] += f2.x; acc[5] += f2.y; acc[6] += f3.x; acc[7] += f3.y;
            }
        }
    }

    #pragma unroll
    for (int u = 0; u < 8; u++)
        hs[g][c * 8 + u] = fmaxf(fmaf(is, acc[u], bs[c * 8 + u]), 0.f);
    __syncthreads();

    if (node >= n) return;
    float a0 = 0.f, a1 = 0.f, a2 = 0.f, a3 = 0.f;
    #pragma unroll
    for (int k = 0; k < H1; k++) {
        float h = hs[g][k];
        a0 = fmaf(h, Ws[k * H2 + c * 4 + 0], a0);
        a1 = fmaf(h, Ws[k * H2 + c * 4 + 1], a1);
        a2 = fmaf(h, Ws[k * H2 + c * 4 + 2], a2);
        a3 = fmaf(h, Ws[k * H2 + c * 4 + 3], a3);
    }
    uint2 o;
    o.x = h2bits(a0 * is, a1 * is);
    o.y = h2bits(a2 * is, a3 * is);
    ((uint2*)(g_y2h + (size_t)node * H2))[c] = o;
}

// ---------------------------------------------------------------------------
// gather2 + bias -> z; 128 threads = 32 nodes x 4 lanes (uint2 rows)
__global__ void __launch_bounds__(128) k_gather2(const float* __restrict__ b2, int n) {
    __shared__ float bs[H2];
    if (threadIdx.x < H2) bs[threadIdx.x] = b2[threadIdx.x];
    __syncthreads();

    int tid = threadIdx.x;
    int g = tid >> 2;
    int c = tid & 3;
    int node = blockIdx.x * 32 + g;
    if (node >= n) return;

    const uint2* y2v = (const uint2*)g_y2h;
    const int4* epad4 = (const int4*)g_epad;
    int base4 = node << (CAPSH - 2);

    uint2 self = y2v[node * 4 + c];
    float acc[4];
    {
        float2 f0 = bits2f(self.x), f1 = bits2f(self.y);
        acc[0] = f0.x; acc[1] = f0.y; acc[2] = f1.x; acc[3] = f1.y;
    }
    int deg = g_cnt[node];
    float is = rsqrtf((float)deg + 1.0f);

    int j = 0;
    for (; j + 8 <= deg; j += 8) {
        int4 i0 = __ldg(&epad4[base4 + (j >> 2)]);
        int4 i1 = __ldg(&epad4[base4 + (j >> 2) + 1]);
        int s[8] = {i0.x, i0.y, i0.z, i0.w, i1.x, i1.y, i1.z, i1.w};
        uint2 v[8];
        #pragma unroll
        for (int u = 0; u < 8; u++) v[u] = y2v[s[u] * 4 + c];
        #pragma unroll
        for (int u = 0; u < 8; u++) {
            float2 f0 = bits2f(v[u].x), f1 = bits2f(v[u].y);
            acc[0] += f0.x; acc[1] += f0.y; acc[2] += f1.x; acc[3] += f1.y;
        }
    }
    if (j < deg) {
        int4 i0 = __ldg(&epad4[base4 + (j >> 2)]);
        int4 i1 = __ldg(&epad4[base4 + (j >> 2) + 1]);
        int s[8] = {i0.x, i0.y, i0.z, i0.w, i1.x, i1.y, i1.z, i1.w};
        int rem = deg - j;
        #pragma unroll
        for (int u = 0; u < 8; u++) {
            if (u < rem) {
                uint2 v0 = y2v[s[u] * 4 + c];
                float2 f0 = bits2f(v0.x), f1 = bits2f(v0.y);
                acc[0] += f0.x; acc[1] += f0.y; acc[2] += f1.x; acc[3] += f1.y;
            }
        }
    }

    float4 z;
    z.x = fmaf(is, acc[0], bs[c * 4 + 0]);
    z.y = fmaf(is, acc[1], bs[c * 4 + 1]);
    z.z = fmaf(is, acc[2], bs[c * 4 + 2]);
    z.w = fmaf(is, acc[3], bs[c * 4 + 3]);
    ((float4*)(g_z + (size_t)node * H2))[c] = z;
}

// ---------------------------------------------------------------------------
// decode: 4 lanes per edge; coalesced float4 row loads + shfl reduce
__global__ void __launch_bounds__(256) k_decode(const int* __restrict__ ea,
                                                const int* __restrict__ eb,
                                                float* __restrict__ out, int L) {
    int t = blockIdx.x * 256 + threadIdx.x;
    int e = t >> 2;
    if (e >= L) return;
    int c = t & 3;
    int a = __ldg(&ea[e]);
    int b = __ldg(&eb[e]);
    float4 u = ((const float4*)g_z)[a * 4 + c];
    float4 v = ((const float4*)g_z)[b * 4 + c];
    float s = u.x * v.x + u.y * v.y + u.z * v.z + u.w * v.w;
    s += __shfl_xor_sync(0xffffffffu, s, 1);
    s += __shfl_xor_sync(0xffffffffu, s, 2);
    if (c == 0) out[e] = s;
}

// ---------------------------------------------------------------------------
extern "C" void kernel_launch(void* const* d_in, const int* in_sizes, int n_in,
                              void* d_out, int out_size) {
    const float* x   = (const float*)d_in[0];
    const int*   ei  = (const int*)  d_in[1];
    const int*   eli = (const int*)  d_in[2];
    const float* W1  = (const float*)d_in[3];
    const float* b1  = (const float*)d_in[4];
    const float* W2  = (const float*)d_in[5];
    const float* b2  = (const float*)d_in[6];
    float* out = (float*)d_out;

    int n = in_sizes[0] / F_IN;     // 100000
    int E = in_sizes[1] / 2;        // 3200000
    int L = in_sizes[2] / 2;        // 200000

    const int* src = ei;
    const int* dst = ei + E;
    const int* ea  = eli;
    const int* eb  = eli + L;

    int gemmBlocks = (n + 255) / 256;            // 391
    int fillBlocks = (E / 8 + 255) / 256;        // 1563

    void* cntPtr = nullptr;
    cudaGetSymbolAddress(&cntPtr, g_cnt);
    cudaMemsetAsync(cntPtr, 0, (size_t)n * sizeof(int));

    k_fuse    <<<gemmBlocks + fillBlocks, 256>>>(x, W1, src, dst, n, E, gemmBlocks);
    k_norm1   <<<(n * 4 + 255) / 256, 256>>>(n);

    k_gather1 <<<(n + 31) / 32, 128>>>(b1, W2, n);
    k_gather2 <<<(n + 31) / 32, 128>>>(b2, n);

    k_decode  <<<((L * 4) + 255) / 256, 256>>>(ea, eb, out, L);
}

// round 12
// speedup vs baseline: 1.2824x; 1.0053x over previous
#include <cuda_runtime.h>
#include <cuda_fp16.h>
#include <cstdint>

// GCN link prediction, round 12: R11 + packed f32x2 accumulation in gathers
// (25% fewer inner-loop instructions) + __ldcs streaming hints on single-use
// inputs (x, src/dst, eli) to preserve L2 for epad/y rows.

#define NMAX  100000
#define EMAX  3200000
#define F_IN  128
#define H1    32
#define H2    16
#define CAP   128
#define CAPSH 7

__device__ __align__(16) int    g_cnt [NMAX];
__device__ __align__(16) int    g_epad[NMAX * CAP];
__device__ __align__(16) __half g_y1h[NMAX * H1];
__device__ __align__(16) __half g_y2h[NMAX * H2];
__device__ __align__(16) float  g_z  [NMAX * H2];

typedef unsigned long long u64;

__device__ __forceinline__ void fma2(u64& acc, u64 a, u64 b) {
    asm("fma.rn.f32x2 %0, %1, %2, %0;" : "+l"(acc) : "l"(a), "l"(b));
}
__device__ __forceinline__ void addp(u64& acc, u64 v) {
    asm("add.rn.f32x2 %0, %0, %1;" : "+l"(acc) : "l"(v));
}
__device__ __forceinline__ u64 pack2(float lo, float hi) {
    u64 r;
    asm("mov.b64 %0, {%1, %2};" : "=l"(r) : "f"(lo), "f"(hi));
    return r;
}
__device__ __forceinline__ float2 unpack2(u64 v) {
    float2 r;
    asm("mov.b64 {%0, %1}, %2;" : "=f"(r.x), "=f"(r.y) : "l"(v));
    return r;
}
__device__ __forceinline__ uint32_t h2bits(float a, float b) {
    __half2 h = __floats2half2_rn(a, b);
    return *(uint32_t*)&h;
}
__device__ __forceinline__ float2 bits2f(uint32_t u) {
    return __half22float2(*(__half2*)&u);
}
__device__ __forceinline__ u64 h2p(uint32_t u) {   // half2 bits -> packed f32x2
    float2 f = __half22float2(*(__half2*)&u);
    return pack2(f.x, f.y);
}

// ---------------------------------------------------------------------------
// fused gemm1 (blocks [0, gemmBlocks)) + fill (remaining blocks)
__global__ void __launch_bounds__(256) k_fuse(const float* __restrict__ x,
                                              const float* __restrict__ W1,
                                              const int* __restrict__ src,
                                              const int* __restrict__ dst,
                                              int n, int E, int gemmBlocks) {
    __shared__ ulonglong2 Ws[F_IN * 8];
    int tid = threadIdx.x;

    if (blockIdx.x < gemmBlocks) {
        const ulonglong2* W1u = (const ulonglong2*)W1;
        #pragma unroll 4
        for (int i = tid; i < F_IN * 8; i += 256) Ws[i] = W1u[i];
        __syncthreads();

        int node = blockIdx.x * 256 + tid;
        if (node >= n) return;

        const float4* xr = (const float4*)(x + (size_t)node * F_IN);

        u64 acc[16];
        #pragma unroll
        for (int i = 0; i < 16; i++) acc[i] = 0ull;

        #pragma unroll
        for (int chunk = 0; chunk < 4; chunk++) {
            float4 xv[8];
            #pragma unroll
            for (int p = 0; p < 8; p++) xv[p] = __ldcs(&xr[chunk * 8 + p]);
            #pragma unroll
            for (int p = 0; p < 8; p++) {
                float xk[4] = {xv[p].x, xv[p].y, xv[p].z, xv[p].w};
                #pragma unroll
                for (int kk = 0; kk < 4; kk++) {
                    int k = chunk * 32 + p * 4 + kk;
                    u64 xp = pack2(xk[kk], xk[kk]);
                    #pragma unroll
                    for (int q = 0; q < 8; q++) {
                        ulonglong2 w = Ws[k * 8 + q];
                        fma2(acc[q * 2],     xp, w.x);
                        fma2(acc[q * 2 + 1], xp, w.y);
                    }
                }
            }
        }

        uint4* yv = (uint4*)(g_y1h + (size_t)node * H1);
        #pragma unroll
        for (int q4 = 0; q4 < 4; q4++) {
            float2 a = unpack2(acc[q4 * 4 + 0]);
            float2 b = unpack2(acc[q4 * 4 + 1]);
            float2 c = unpack2(acc[q4 * 4 + 2]);
            float2 d = unpack2(acc[q4 * 4 + 3]);
            uint4 o;
            o.x = h2bits(a.x, a.y);
            o.y = h2bits(b.x, b.y);
            o.z = h2bits(c.x, c.y);
            o.w = h2bits(d.x, d.y);
            yv[q4] = o;
        }
    } else {
        int t = (blockIdx.x - gemmBlocks) * 256 + tid;
        if (t * 8 >= E) return;
        int4 d0 = __ldcs(&((const int4*)dst)[t * 2]);
        int4 d1 = __ldcs(&((const int4*)dst)[t * 2 + 1]);
        int4 s0 = __ldcs(&((const int4*)src)[t * 2]);
        int4 s1 = __ldcs(&((const int4*)src)[t * 2 + 1]);

        int dd[8] = {d0.x, d0.y, d0.z, d0.w, d1.x, d1.y, d1.z, d1.w};
        int ss[8] = {s0.x, s0.y, s0.z, s0.w, s1.x, s1.y, s1.z, s1.w};

        int pos[8];
        #pragma unroll
        for (int u = 0; u < 8; u++) pos[u] = atomicAdd(&g_cnt[dd[u]], 1);
        #pragma unroll
        for (int u = 0; u < 8; u++) {
            int p = pos[u] < CAP ? pos[u] : (CAP - 1);
            g_epad[(dd[u] << CAPSH) + p] = ss[u];
        }
    }
}

// ---------------------------------------------------------------------------
__global__ void __launch_bounds__(256) k_norm1(int n) {
    int t = blockIdx.x * 256 + threadIdx.x;
    int node = t >> 2;
    if (node >= n) return;
    int c = t & 3;
    float is = rsqrtf((float)g_cnt[node] + 1.0f);
    uint4* yv = (uint4*)(g_y1h + (size_t)node * H1);
    uint4 v = yv[c];
    float2 f0 = bits2f(v.x), f1 = bits2f(v.y), f2 = bits2f(v.z), f3 = bits2f(v.w);
    uint4 o;
    o.x = h2bits(f0.x * is, f0.y * is);
    o.y = h2bits(f1.x * is, f1.y * is);
    o.z = h2bits(f2.x * is, f2.y * is);
    o.w = h2bits(f3.x * is, f3.y * is);
    yv[c] = o;
}

// ---------------------------------------------------------------------------
// gather1 + relu/bias + GEMM2 -> y2h; 128 threads = 32 nodes x 4 lanes
__global__ void __launch_bounds__(128) k_gather1(const float* __restrict__ b1,
                                                 const float* __restrict__ W2, int n) {
    __shared__ float Ws[H1 * H2];
    __shared__ float bs[H1];
    __shared__ float hs[32][H1 + 2];

    int tid = threadIdx.x;
    for (int i = tid; i < H1 * H2 / 2; i += 128) ((float2*)Ws)[i] = ((const float2*)W2)[i];
    if (tid < H1) bs[tid] = b1[tid];
    __syncthreads();

    int g = tid >> 2;
    int c = tid & 3;
    int node = blockIdx.x * 32 + g;

    u64 accp[4];
    #pragma unroll
    for (int i = 0; i < 4; i++) accp[i] = 0ull;
    float is = 0.f;
    int deg = 0;
    const uint4* y1v = (const uint4*)g_y1h;
    const int4* epad4 = (const int4*)g_epad;
    int base4 = node << (CAPSH - 2);

    if (node < n) {
        uint4 self = y1v[node * 4 + c];
        accp[0] = h2p(self.x); accp[1] = h2p(self.y);
        accp[2] = h2p(self.z); accp[3] = h2p(self.w);
        deg = g_cnt[node];
        is = rsqrtf((float)deg + 1.0f);
    }

    int j = 0;
    for (; j + 8 <= deg; j += 8) {
        int4 i0 = __ldg(&epad4[base4 + (j >> 2)]);
        int4 i1 = __ldg(&epad4[base4 + (j >> 2) + 1]);
        int s[8] = {i0.x, i0.y, i0.z, i0.w, i1.x, i1.y, i1.z, i1.w};
        uint4 v[8];
        #pragma unroll
        for (int u = 0; u < 8; u++) v[u] = y1v[s[u] * 4 + c];
        #pragma unroll
        for (int u = 0; u < 8; u++) {
            addp(accp[0], h2p(v[u].x));
            addp(accp[1], h2p(v[u].y));
            addp(accp[2], h2p(v[u].z));
            addp(accp[3], h2p(v[u].w));
        }
    }
    if (j < deg) {
        int4 i0 = __ldg(&epad4[base4 + (j >> 2)]);
        int4 i1 = __ldg(&epad4[base4 + (j >> 2) + 1]);
        int s[8] = {i0.x, i0.y, i0.z, i0.w, i1.x, i1.y, i1.z, i1.w};
        int rem = deg - j;
        #pragma unroll
        for (int u = 0; u < 8; u++) {
            if (u < rem) {
                uint4 v0 = y1v[s[u] * 4 + c];
                addp(accp[0], h2p(v0.x));
                addp(accp[1], h2p(v0.y));
                addp(accp[2], h2p(v0.z));
                addp(accp[3], h2p(v0.w));
            }
        }
    }

    #pragma unroll
    for (int q = 0; q < 4; q++) {
        float2 f = unpack2(accp[q]);
        hs[g][c * 8 + q * 2 + 0] = fmaxf(fmaf(is, f.x, bs[c * 8 + q * 2 + 0]), 0.f);
        hs[g][c * 8 + q * 2 + 1] = fmaxf(fmaf(is, f.y, bs[c * 8 + q * 2 + 1]), 0.f);
    }
    __syncthreads();

    if (node >= n) return;
    float a0 = 0.f, a1 = 0.f, a2 = 0.f, a3 = 0.f;
    #pragma unroll
    for (int k = 0; k < H1; k++) {
        float h = hs[g][k];
        a0 = fmaf(h, Ws[k * H2 + c * 4 + 0], a0);
        a1 = fmaf(h, Ws[k * H2 + c * 4 + 1], a1);
        a2 = fmaf(h, Ws[k * H2 + c * 4 + 2], a2);
        a3 = fmaf(h, Ws[k * H2 + c * 4 + 3], a3);
    }
    uint2 o;
    o.x = h2bits(a0 * is, a1 * is);
    o.y = h2bits(a2 * is, a3 * is);
    ((uint2*)(g_y2h + (size_t)node * H2))[c] = o;
}

// ---------------------------------------------------------------------------
// gather2 + bias -> z; 128 threads = 32 nodes x 4 lanes (uint2 rows)
__global__ void __launch_bounds__(128) k_gather2(const float* __restrict__ b2, int n) {
    __shared__ float bs[H2];
    if (threadIdx.x < H2) bs[threadIdx.x] = b2[threadIdx.x];
    __syncthreads();

    int tid = threadIdx.x;
    int g = tid >> 2;
    int c = tid & 3;
    int node = blockIdx.x * 32 + g;
    if (node >= n) return;

    const uint2* y2v = (const uint2*)g_y2h;
    const int4* epad4 = (const int4*)g_epad;
    int base4 = node << (CAPSH - 2);

    uint2 self = y2v[node * 4 + c];
    u64 accp[2];
    accp[0] = h2p(self.x);
    accp[1] = h2p(self.y);
    int deg = g_cnt[node];
    float is = rsqrtf((float)deg + 1.0f);

    int j = 0;
    for (; j + 8 <= deg; j += 8) {
        int4 i0 = __ldg(&epad4[base4 + (j >> 2)]);
        int4 i1 = __ldg(&epad4[base4 + (j >> 2) + 1]);
        int s[8] = {i0.x, i0.y, i0.z, i0.w, i1.x, i1.y, i1.z, i1.w};
        uint2 v[8];
        #pragma unroll
        for (int u = 0; u < 8; u++) v[u] = y2v[s[u] * 4 + c];
        #pragma unroll
        for (int u = 0; u < 8; u++) {
            addp(accp[0], h2p(v[u].x));
            addp(accp[1], h2p(v[u].y));
        }
    }
    if (j < deg) {
        int4 i0 = __ldg(&epad4[base4 + (j >> 2)]);
        int4 i1 = __ldg(&epad4[base4 + (j >> 2) + 1]);
        int s[8] = {i0.x, i0.y, i0.z, i0.w, i1.x, i1.y, i1.z, i1.w};
        int rem = deg - j;
        #pragma unroll
        for (int u = 0; u < 8; u++) {
            if (u < rem) {
                uint2 v0 = y2v[s[u] * 4 + c];
                addp(accp[0], h2p(v0.x));
                addp(accp[1], h2p(v0.y));
            }
        }
    }

    float2 f0 = unpack2(accp[0]);
    float2 f1 = unpack2(accp[1]);
    float4 z;
    z.x = fmaf(is, f0.x, bs[c * 4 + 0]);
    z.y = fmaf(is, f0.y, bs[c * 4 + 1]);
    z.z = fmaf(is, f1.x, bs[c * 4 + 2]);
    z.w = fmaf(is, f1.y, bs[c * 4 + 3]);
    ((float4*)(g_z + (size_t)node * H2))[c] = z;
}

// ---------------------------------------------------------------------------
// decode: 4 lanes per edge; coalesced float4 row loads + shfl reduce
__global__ void __launch_bounds__(256) k_decode(const int* __restrict__ ea,
                                                const int* __restrict__ eb,
                                                float* __restrict__ out, int L) {
    int t = blockIdx.x * 256 + threadIdx.x;
    int e = t >> 2;
    if (e >= L) return;
    int c = t & 3;
    int a = __ldcs(&ea[e]);
    int b = __ldcs(&eb[e]);
    float4 u = ((const float4*)g_z)[a * 4 + c];
    float4 v = ((const float4*)g_z)[b * 4 + c];
    float s = u.x * v.x + u.y * v.y + u.z * v.z + u.w * v.w;
    s += __shfl_xor_sync(0xffffffffu, s, 1);
    s += __shfl_xor_sync(0xffffffffu, s, 2);
    if (c == 0) out[e] = s;
}

// ---------------------------------------------------------------------------
extern "C" void kernel_launch(void* const* d_in, const int* in_sizes, int n_in,
                              void* d_out, int out_size) {
    const float* x   = (const float*)d_in[0];
    const int*   ei  = (const int*)  d_in[1];
    const int*   eli = (const int*)  d_in[2];
    const float* W1  = (const float*)d_in[3];
    const float* b1  = (const float*)d_in[4];
    const float* W2  = (const float*)d_in[5];
    const float* b2  = (const float*)d_in[6];
    float* out = (float*)d_out;

    int n = in_sizes[0] / F_IN;     // 100000
    int E = in_sizes[1] / 2;        // 3200000
    int L = in_sizes[2] / 2;        // 200000

    const int* src = ei;
    const int* dst = ei + E;
    const int* ea  = eli;
    const int* eb  = eli + L;

    int gemmBlocks = (n + 255) / 256;            // 391
    int fillBlocks = (E / 8 + 255) / 256;        // 1563

    void* cntPtr = nullptr;
    cudaGetSymbolAddress(&cntPtr, g_cnt);
    cudaMemsetAsync(cntPtr, 0, (size_t)n * sizeof(int));

    k_fuse    <<<gemmBlocks + fillBlocks, 256>>>(x, W1, src, dst, n, E, gemmBlocks);
    k_norm1   <<<(n * 4 + 255) / 256, 256>>>(n);

    k_gather1 <<<(n + 31) / 32, 128>>>(b1, W2, n);
    k_gather2 <<<(n + 31) / 32, 128>>>(b2, n);

    k_decode  <<<((L * 4) + 255) / 256, 256>>>(ea, eb, out, L);
}

// round 13
// speedup vs baseline: 1.3203x; 1.0296x over previous
#include <cuda_runtime.h>
#include <cuda_fp16.h>
#include <cstdint>

// GCN link prediction, round 13: R12 kernels + Programmatic Dependent Launch
// (PDL) on the dependency chain fuse -> norm1 -> gather1 -> gather2 -> decode.
// Each dependent kernel runs its dependency-free prologue during the
// predecessor's tail, then blocks at cudaGridDependencySynchronize().

#define NMAX  100000
#define EMAX  3200000
#define F_IN  128
#define H1    32
#define H2    16
#define CAP   128
#define CAPSH 7

__device__ __align__(16) int    g_cnt [NMAX];
__device__ __align__(16) int    g_epad[NMAX * CAP];
__device__ __align__(16) __half g_y1h[NMAX * H1];
__device__ __align__(16) __half g_y2h[NMAX * H2];
__device__ __align__(16) float  g_z  [NMAX * H2];

typedef unsigned long long u64;

__device__ __forceinline__ void fma2(u64& acc, u64 a, u64 b) {
    asm("fma.rn.f32x2 %0, %1, %2, %0;" : "+l"(acc) : "l"(a), "l"(b));
}
__device__ __forceinline__ void addp(u64& acc, u64 v) {
    asm("add.rn.f32x2 %0, %0, %1;" : "+l"(acc) : "l"(v));
}
__device__ __forceinline__ u64 pack2(float lo, float hi) {
    u64 r;
    asm("mov.b64 %0, {%1, %2};" : "=l"(r) : "f"(lo), "f"(hi));
    return r;
}
__device__ __forceinline__ float2 unpack2(u64 v) {
    float2 r;
    asm("mov.b64 {%0, %1}, %2;" : "=f"(r.x), "=f"(r.y) : "l"(v));
    return r;
}
__device__ __forceinline__ uint32_t h2bits(float a, float b) {
    __half2 h = __floats2half2_rn(a, b);
    return *(uint32_t*)&h;
}
__device__ __forceinline__ float2 bits2f(uint32_t u) {
    return __half22float2(*(__half2*)&u);
}
__device__ __forceinline__ u64 h2p(uint32_t u) {
    float2 f = __half22float2(*(__half2*)&u);
    return pack2(f.x, f.y);
}

// ---------------------------------------------------------------------------
// fused gemm1 (blocks [0, gemmBlocks)) + fill (remaining blocks)
__global__ void __launch_bounds__(256) k_fuse(const float* __restrict__ x,
                                              const float* __restrict__ W1,
                                              const int* __restrict__ src,
                                              const int* __restrict__ dst,
                                              int n, int E, int gemmBlocks) {
    __shared__ ulonglong2 Ws[F_IN * 8];
    int tid = threadIdx.x;

    if (blockIdx.x < gemmBlocks) {
        const ulonglong2* W1u = (const ulonglong2*)W1;
        #pragma unroll 4
        for (int i = tid; i < F_IN * 8; i += 256) Ws[i] = W1u[i];
        __syncthreads();

        int node = blockIdx.x * 256 + tid;
        if (node >= n) return;

        const float4* xr = (const float4*)(x + (size_t)node * F_IN);

        u64 acc[16];
        #pragma unroll
        for (int i = 0; i < 16; i++) acc[i] = 0ull;

        #pragma unroll
        for (int chunk = 0; chunk < 4; chunk++) {
            float4 xv[8];
            #pragma unroll
            for (int p = 0; p < 8; p++) xv[p] = __ldcs(&xr[chunk * 8 + p]);
            #pragma unroll
            for (int p = 0; p < 8; p++) {
                float xk[4] = {xv[p].x, xv[p].y, xv[p].z, xv[p].w};
                #pragma unroll
                for (int kk = 0; kk < 4; kk++) {
                    int k = chunk * 32 + p * 4 + kk;
                    u64 xp = pack2(xk[kk], xk[kk]);
                    #pragma unroll
                    for (int q = 0; q < 8; q++) {
                        ulonglong2 w = Ws[k * 8 + q];
                        fma2(acc[q * 2],     xp, w.x);
                        fma2(acc[q * 2 + 1], xp, w.y);
                    }
                }
            }
        }

        uint4* yv = (uint4*)(g_y1h + (size_t)node * H1);
        #pragma unroll
        for (int q4 = 0; q4 < 4; q4++) {
            float2 a = unpack2(acc[q4 * 4 + 0]);
            float2 b = unpack2(acc[q4 * 4 + 1]);
            float2 c = unpack2(acc[q4 * 4 + 2]);
            float2 d = unpack2(acc[q4 * 4 + 3]);
            uint4 o;
            o.x = h2bits(a.x, a.y);
            o.y = h2bits(b.x, b.y);
            o.z = h2bits(c.x, c.y);
            o.w = h2bits(d.x, d.y);
            yv[q4] = o;
        }
    } else {
        int t = (blockIdx.x - gemmBlocks) * 256 + tid;
        if (t * 8 >= E) return;
        int4 d0 = __ldcs(&((const int4*)dst)[t * 2]);
        int4 d1 = __ldcs(&((const int4*)dst)[t * 2 + 1]);
        int4 s0 = __ldcs(&((const int4*)src)[t * 2]);
        int4 s1 = __ldcs(&((const int4*)src)[t * 2 + 1]);

        int dd[8] = {d0.x, d0.y, d0.z, d0.w, d1.x, d1.y, d1.z, d1.w};
        int ss[8] = {s0.x, s0.y, s0.z, s0.w, s1.x, s1.y, s1.z, s1.w};

        int pos[8];
        #pragma unroll
        for (int u = 0; u < 8; u++) pos[u] = atomicAdd(&g_cnt[dd[u]], 1);
        #pragma unroll
        for (int u = 0; u < 8; u++) {
            int p = pos[u] < CAP ? pos[u] : (CAP - 1);
            g_epad[(dd[u] << CAPSH) + p] = ss[u];
        }
    }
}

// ---------------------------------------------------------------------------
__global__ void __launch_bounds__(256) k_norm1(int n) {
    int t = blockIdx.x * 256 + threadIdx.x;
    int node = t >> 2;
    int c = t & 3;
    cudaGridDependencySynchronize();          // wait for fuse (cnt + y1h)
    if (node >= n) return;
    float is = rsqrtf((float)g_cnt[node] + 1.0f);
    uint4* yv = (uint4*)(g_y1h + (size_t)node * H1);
    uint4 v = yv[c];
    float2 f0 = bits2f(v.x), f1 = bits2f(v.y), f2 = bits2f(v.z), f3 = bits2f(v.w);
    uint4 o;
    o.x = h2bits(f0.x * is, f0.y * is);
    o.y = h2bits(f1.x * is, f1.y * is);
    o.z = h2bits(f2.x * is, f2.y * is);
    o.w = h2bits(f3.x * is, f3.y * is);
    yv[c] = o;
}

// ---------------------------------------------------------------------------
// gather1 + relu/bias + GEMM2 -> y2h; 128 threads = 32 nodes x 4 lanes
__global__ void __launch_bounds__(128) k_gather1(const float* __restrict__ b1,
                                                 const float* __restrict__ W2, int n) {
    __shared__ float Ws[H1 * H2];
    __shared__ float bs[H1];
    __shared__ float hs[32][H1 + 2];

    int tid = threadIdx.x;
    // prologue: W2/b1 are harness inputs, independent of norm1
    for (int i = tid; i < H1 * H2 / 2; i += 128) ((float2*)Ws)[i] = ((const float2*)W2)[i];
    if (tid < H1) bs[tid] = b1[tid];
    cudaGridDependencySynchronize();          // wait for norm1 (y1h normalized)
    __syncthreads();

    int g = tid >> 2;
    int c = tid & 3;
    int node = blockIdx.x * 32 + g;

    u64 accp[4];
    #pragma unroll
    for (int i = 0; i < 4; i++) accp[i] = 0ull;
    float is = 0.f;
    int deg = 0;
    const uint4* y1v = (const uint4*)g_y1h;
    const int4* epad4 = (const int4*)g_epad;
    int base4 = node << (CAPSH - 2);

    if (node < n) {
        uint4 self = y1v[node * 4 + c];
        accp[0] = h2p(self.x); accp[1] = h2p(self.y);
        accp[2] = h2p(self.z); accp[3] = h2p(self.w);
        deg = g_cnt[node];
        is = rsqrtf((float)deg + 1.0f);
    }

    int j = 0;
    for (; j + 8 <= deg; j += 8) {
        int4 i0 = __ldg(&epad4[base4 + (j >> 2)]);
        int4 i1 = __ldg(&epad4[base4 + (j >> 2) + 1]);
        int s[8] = {i0.x, i0.y, i0.z, i0.w, i1.x, i1.y, i1.z, i1.w};
        uint4 v[8];
        #pragma unroll
        for (int u = 0; u < 8; u++) v[u] = y1v[s[u] * 4 + c];
        #pragma unroll
        for (int u = 0; u < 8; u++) {
            addp(accp[0], h2p(v[u].x));
            addp(accp[1], h2p(v[u].y));
            addp(accp[2], h2p(v[u].z));
            addp(accp[3], h2p(v[u].w));
        }
    }
    if (j < deg) {
        int4 i0 = __ldg(&epad4[base4 + (j >> 2)]);
        int4 i1 = __ldg(&epad4[base4 + (j >> 2) + 1]);
        int s[8] = {i0.x, i0.y, i0.z, i0.w, i1.x, i1.y, i1.z, i1.w};
        int rem = deg - j;
        #pragma unroll
        for (int u = 0; u < 8; u++) {
            if (u < rem) {
                uint4 v0 = y1v[s[u] * 4 + c];
                addp(accp[0], h2p(v0.x));
                addp(accp[1], h2p(v0.y));
                addp(accp[2], h2p(v0.z));
                addp(accp[3], h2p(v0.w));
            }
        }
    }

    #pragma unroll
    for (int q = 0; q < 4; q++) {
        float2 f = unpack2(accp[q]);
        hs[g][c * 8 + q * 2 + 0] = fmaxf(fmaf(is, f.x, bs[c * 8 + q * 2 + 0]), 0.f);
        hs[g][c * 8 + q * 2 + 1] = fmaxf(fmaf(is, f.y, bs[c * 8 + q * 2 + 1]), 0.f);
    }
    __syncthreads();

    if (node >= n) return;
    float a0 = 0.f, a1 = 0.f, a2 = 0.f, a3 = 0.f;
    #pragma unroll
    for (int k = 0; k < H1; k++) {
        float h = hs[g][k];
        a0 = fmaf(h, Ws[k * H2 + c * 4 + 0], a0);
        a1 = fmaf(h, Ws[k * H2 + c * 4 + 1], a1);
        a2 = fmaf(h, Ws[k * H2 + c * 4 + 2], a2);
        a3 = fmaf(h, Ws[k * H2 + c * 4 + 3], a3);
    }
    uint2 o;
    o.x = h2bits(a0 * is, a1 * is);
    o.y = h2bits(a2 * is, a3 * is);
    ((uint2*)(g_y2h + (size_t)node * H2))[c] = o;
}

// ---------------------------------------------------------------------------
// gather2 + bias -> z; 128 threads = 32 nodes x 4 lanes (uint2 rows)
__global__ void __launch_bounds__(128) k_gather2(const float* __restrict__ b2, int n) {
    __shared__ float bs[H2];
    if (threadIdx.x < H2) bs[threadIdx.x] = b2[threadIdx.x];   // input, independent
    cudaGridDependencySynchronize();          // wait for gather1 (y2h)
    __syncthreads();

    int tid = threadIdx.x;
    int g = tid >> 2;
    int c = tid & 3;
    int node = blockIdx.x * 32 + g;
    if (node >= n) return;

    const uint2* y2v = (const uint2*)g_y2h;
    const int4* epad4 = (const int4*)g_epad;
    int base4 = node << (CAPSH - 2);

    uint2 self = y2v[node * 4 + c];
    u64 accp[2];
    accp[0] = h2p(self.x);
    accp[1] = h2p(self.y);
    int deg = g_cnt[node];
    float is = rsqrtf((float)deg + 1.0f);

    int j = 0;
    for (; j + 8 <= deg; j += 8) {
        int4 i0 = __ldg(&epad4[base4 + (j >> 2)]);
        int4 i1 = __ldg(&epad4[base4 + (j >> 2) + 1]);
        int s[8] = {i0.x, i0.y, i0.z, i0.w, i1.x, i1.y, i1.z, i1.w};
        uint2 v[8];
        #pragma unroll
        for (int u = 0; u < 8; u++) v[u] = y2v[s[u] * 4 + c];
        #pragma unroll
        for (int u = 0; u < 8; u++) {
            addp(accp[0], h2p(v[u].x));
            addp(accp[1], h2p(v[u].y));
        }
    }
    if (j < deg) {
        int4 i0 = __ldg(&epad4[base4 + (j >> 2)]);
        int4 i1 = __ldg(&epad4[base4 + (j >> 2) + 1]);
        int s[8] = {i0.x, i0.y, i0.z, i0.w, i1.x, i1.y, i1.z, i1.w};
        int rem = deg - j;
        #pragma unroll
        for (int u = 0; u < 8; u++) {
            if (u < rem) {
                uint2 v0 = y2v[s[u] * 4 + c];
                addp(accp[0], h2p(v0.x));
                addp(accp[1], h2p(v0.y));
            }
        }
    }

    float2 f0 = unpack2(accp[0]);
    float2 f1 = unpack2(accp[1]);
    float4 z;
    z.x = fmaf(is, f0.x, bs[c * 4 + 0]);
    z.y = fmaf(is, f0.y, bs[c * 4 + 1]);
    z.z = fmaf(is, f1.x, bs[c * 4 + 2]);
    z.w = fmaf(is, f1.y, bs[c * 4 + 3]);
    ((float4*)(g_z + (size_t)node * H2))[c] = z;
}

// ---------------------------------------------------------------------------
// decode: 4 lanes per edge; index loads (inputs) before griddepsync
__global__ void __launch_bounds__(256) k_decode(const int* __restrict__ ea,
                                                const int* __restrict__ eb,
                                                float* __restrict__ out, int L) {
    int t = blockIdx.x * 256 + threadIdx.x;
    int e = t >> 2;
    int c = t & 3;
    int a = 0, b = 0;
    if (e < L) {
        a = __ldcs(&ea[e]);              // prologue: inputs, independent of gather2
        b = __ldcs(&eb[e]);
    }
    cudaGridDependencySynchronize();     // wait for gather2 (g_z)
    if (e >= L) return;
    float4 u = ((const float4*)g_z)[a * 4 + c];
    float4 v = ((const float4*)g_z)[b * 4 + c];
    float s = u.x * v.x + u.y * v.y + u.z * v.z + u.w * v.w;
    s += __shfl_xor_sync(0xffffffffu, s, 1);
    s += __shfl_xor_sync(0xffffffffu, s, 2);
    if (c == 0) out[e] = s;
}

// ---------------------------------------------------------------------------
template <typename F, typename... Args>
static inline void launch_pdl(F func, dim3 grid, dim3 block, Args... args) {
    cudaLaunchConfig_t cfg = {};
    cfg.gridDim = grid;
    cfg.blockDim = block;
    cudaLaunchAttribute attr[1];
    attr[0].id = cudaLaunchAttributeProgrammaticStreamSerialization;
    attr[0].val.programmaticStreamSerializationAllowed = 1;
    cfg.attrs = attr;
    cfg.numAttrs = 1;
    cudaLaunchKernelEx(&cfg, func, args...);
}

extern "C" void kernel_launch(void* const* d_in, const int* in_sizes, int n_in,
                              void* d_out, int out_size) {
    const float* x   = (const float*)d_in[0];
    const int*   ei  = (const int*)  d_in[1];
    const int*   eli = (const int*)  d_in[2];
    const float* W1  = (const float*)d_in[3];
    const float* b1  = (const float*)d_in[4];
    const float* W2  = (const float*)d_in[5];
    const float* b2  = (const float*)d_in[6];
    float* out = (float*)d_out;

    int n = in_sizes[0] / F_IN;     // 100000
    int E = in_sizes[1] / 2;        // 3200000
    int L = in_sizes[2] / 2;        // 200000

    const int* src = ei;
    const int* dst = ei + E;
    const int* ea  = eli;
    const int* eb  = eli + L;

    int gemmBlocks = (n + 255) / 256;            // 391
    int fillBlocks = (E / 8 + 255) / 256;        // 1563

    void* cntPtr = nullptr;
    cudaGetSymbolAddress(&cntPtr, g_cnt);
    cudaMemsetAsync(cntPtr, 0, (size_t)n * sizeof(int));

    k_fuse<<<gemmBlocks + fillBlocks, 256>>>(x, W1, src, dst, n, E, gemmBlocks);

    launch_pdl(k_norm1,   dim3((n * 4 + 255) / 256), dim3(256), n);
    launch_pdl(k_gather1, dim3((n + 31) / 32),       dim3(128), b1, W2, n);
    launch_pdl(k_gather2, dim3((n + 31) / 32),       dim3(128), b2, n);
    launch_pdl(k_decode,  dim3((L * 4 + 255) / 256), dim3(256), ea, eb, out, L);
}